// round 10
// baseline (speedup 1.0000x reference)
#include <cuda_runtime.h>
#include <cstdio>
#include <cstdint>

#define NTHREADS 256
#define NBLOCKS  4096            // 4096*256 threads = 1,048,576 groups of 16
#define NEED_X   16777216u       // floats in x
#define NEED_OUT 16777216u       // floats in output (real part of Z)

// Complex work buffer (128 MB). Statics were exonerated in rounds 5-9.
__device__ float2 g_buf[(size_t)NEED_X];

__device__ __forceinline__ float2 cmul(float2 a, float2 b) {
    return make_float2(fmaf(a.x, b.x, -a.y * b.y), fmaf(a.x, b.y, a.y * b.x));
}

__device__ __forceinline__ float2 cmadd2(float2 g0, float2 a, float2 g1, float2 b) {
    float re = fmaf(g0.x, a.x, -g0.y * a.y);
    re = fmaf(g1.x, b.x, re);
    re = fmaf(-g1.y, b.y, re);
    float im = fmaf(g0.x, a.y, g0.y * a.x);
    im = fmaf(g1.x, b.y, im);
    im = fmaf(g1.y, b.x, im);
    return make_float2(re, im);
}

// ---------------------------------------------------------------------------
// ONE kernel, 6 launches, mode flags at runtime.
//   realin  : read 16 floats of x (stride S=1), convert to complex
//   realout : write real part only, as float, into dout (FINAL sweep)
//   else    : complex in/out on g_buf, in place
// Thread 0 per block rebuilds this pass's 4 gates from w (guarded reads).
// Group for thread gt: base = (gt/S)*16S + gt%S, elements base + i*S.
// Exact partition of [0, 2^24) -> in-place safe.
// pass p acts on transform-dim bits 4p..4p+3; qubit q acts on bit 11-q.
// ---------------------------------------------------------------------------
__global__ void __launch_bounds__(NTHREADS)
sweep_any(const float* __restrict__ x, float* __restrict__ dout,
          const float* __restrict__ w,
          int pass, int cj, int realin, int realout, unsigned S,
          unsigned wlim, unsigned xlim, unsigned olim)
{
    __shared__ float2 Gs[4][4];
    if (threadIdx.x == 0) {
        const float WM = 0.63245553203367586640f;  // sqrt(2/5)
        for (int s = 0; s < 4; s++) {
            int q = 11 - (4 * pass + s);
            float a0 = (unsigned)(3 * q + 0) < wlim ? w[3 * q + 0] : 0.f;
            float a1 = (unsigned)(3 * q + 1) < wlim ? w[3 * q + 1] : 0.f;
            float a2 = (unsigned)(3 * q + 2) < wlim ? w[3 * q + 2] : 0.f;
            float hx = 0.5f * a0 * WM, hy = 0.5f * a1 * WM, hz = 0.5f * a2 * WM;
            float cx, sx, cy, sy, cz, sz;
            sincosf(hx, &sx, &cx);
            sincosf(hy, &sy, &cy);
            sincosf(hz, &sz, &cz);
            // ry @ rx
            float2 m0 = make_float2(cy * cx, sy * sx);
            float2 m1 = make_float2(-sy * cx, -cy * sx);
            float2 m2 = make_float2(sy * cx, -cy * sx);
            float2 m3 = make_float2(cy * cx, -sy * sx);
            float2 ez  = make_float2(cz, -sz);   // e^{-i hz}
            float2 ezc = make_float2(cz,  sz);   // e^{+i hz}
            float2 u0 = cmul(ez, m0),  u1 = cmul(ez, m1);
            float2 u2 = cmul(ezc, m2), u3 = cmul(ezc, m3);
            float sgn = cj ? -1.f : 1.f;
            Gs[s][0] = make_float2(u0.x, sgn * u0.y);
            Gs[s][1] = make_float2(u1.x, sgn * u1.y);
            Gs[s][2] = make_float2(u2.x, sgn * u2.y);
            Gs[s][3] = make_float2(u3.x, sgn * u3.y);
        }
    }
    __syncthreads();

    float2 G[4][4];
#pragma unroll
    for (int s = 0; s < 4; s++)
#pragma unroll
        for (int e = 0; e < 4; e++) G[s][e] = Gs[s][e];

    unsigned gt = blockIdx.x * NTHREADS + threadIdx.x;   // 0 .. 1,048,575
    size_t base = (size_t)(gt / S) * (16u * (size_t)S) + (gt % S);

    float2 v[16];
    if (realin) {
#pragma unroll
        for (int i = 0; i < 16; i++) {
            size_t idx = base + (size_t)i * S;
            v[i] = make_float2(idx < xlim ? x[idx] : 0.f, 0.f);
        }
    } else {
#pragma unroll
        for (int i = 0; i < 16; i++) {
            size_t idx = base + (size_t)i * S;
            v[i] = idx < (size_t)NEED_X ? g_buf[idx] : make_float2(0.f, 0.f);
        }
    }

    // 4 gate stages on 16 register values (stage s pairs k, k+2^s)
#pragma unroll
    for (int s = 0; s < 4; s++) {
        int str = 1 << s;
#pragma unroll
        for (int k = 0; k < 16; k++) {
            if ((k & str) == 0) {
                float2 a = v[k], b = v[k + str];
                float2 n0 = cmadd2(G[s][0], a, G[s][1], b);
                float2 n1 = cmadd2(G[s][2], a, G[s][3], b);
                v[k] = n0;
                v[k + str] = n1;
            }
        }
    }

    if (realout) {
        // FINAL sweep: only place d_out is ever touched. Float stores, guarded
        // in FLOAT units -> max 64 MB written, safe under any dtype convention.
#pragma unroll
        for (int i = 0; i < 16; i++) {
            size_t idx = base + (size_t)i * S;
            if (idx < olim) dout[idx] = v[i].x;
        }
    } else {
#pragma unroll
        for (int i = 0; i < 16; i++) {
            size_t idx = base + (size_t)i * S;
            if (idx < (size_t)NEED_X) g_buf[idx] = v[i];
        }
    }
}

// ---------------------------------------------------------------------------
extern "C" void kernel_launch(void* const* d_in, const int* in_sizes, int n_in,
                              void* d_out, int out_size) {
    // All diagnostics to STDERR (round 8/9 comparison: error text = stderr).
    fprintf(stderr, "DIAG n_in=%d out_size=%d d_out=%p\n", n_in, out_size, d_out);
    for (int i = 0; i < n_in && i < 8; i++)
        fprintf(stderr, "DIAG in[%d] size=%d ptr=%p\n", i, in_sizes[i], d_in[i]);
    fflush(stderr);

    // weight = strictly smaller input
    const float* w = (const float*)d_in[0];
    const float* x = (const float*)d_in[0];
    long long wsz = 0, xsz = 0;
    if (n_in >= 2) {
        if ((long long)in_sizes[0] <= (long long)in_sizes[1]) {
            w = (const float*)d_in[0]; wsz = in_sizes[0];
            x = (const float*)d_in[1]; xsz = in_sizes[1];
        } else {
            w = (const float*)d_in[1]; wsz = in_sizes[1];
            x = (const float*)d_in[0]; xsz = in_sizes[0];
        }
    } else if (n_in == 1) {
        x = (const float*)d_in[0]; xsz = in_sizes[0];
    }
    if (wsz < 0) wsz = 0;
    if (xsz < 0) xsz = 0;
    long long osz = out_size;
    if (osz < 0) osz = 0;

    unsigned wlim = (unsigned)(wsz > 36 ? 36 : wsz);
    unsigned xlim = (unsigned)(xsz > (long long)NEED_X ? (long long)NEED_X : xsz);
    unsigned olim = (unsigned)(osz > (long long)NEED_OUT ? (long long)NEED_OUT : osz);

    float* dout = (float*)d_out;

    cudaStreamCaptureStatus st = cudaStreamCaptureStatusNone;
    cudaStreamIsCapturing((cudaStream_t)0, &st);
    const bool can_sync = (st == cudaStreamCaptureStatusNone);

#define LAUNCH_CK(tag, p, cj, ri, ro, S)                                      \
    do {                                                                      \
        sweep_any<<<NBLOCKS, NTHREADS>>>(x, dout, w, p, cj, ri, ro, S,        \
                                         wlim, xlim, olim);                   \
        cudaError_t le_ = cudaGetLastError();                                 \
        if (can_sync) {                                                       \
            cudaError_t se_ = cudaStreamSynchronize((cudaStream_t)0);         \
            fprintf(stderr, "DIAG %s launch=%s sync=%s\n", tag,               \
                    cudaGetErrorName(le_), cudaGetErrorName(se_));            \
            fflush(stderr);                                                   \
        }                                                                     \
    } while (0)

    // ---- Side 1: Y = x U^H (conj gates along column bits), into g_buf ----
    LAUNCH_CK("sweep0", 0, 1, 1, 0, 1u);        // x -> g_buf, col bits 0-3
    LAUNCH_CK("sweep1", 1, 1, 0, 0, 16u);       // col bits 4-7
    LAUNCH_CK("sweep2", 2, 1, 0, 0, 256u);      // col bits 8-11
    // ---- Side 2: Z = U Y (plain gates along row bits) ----
    LAUNCH_CK("sweep3", 0, 0, 0, 0, 4096u);     // row bits 0-3
    LAUNCH_CK("sweep4", 1, 0, 0, 0, 65536u);    // row bits 4-7
    LAUNCH_CK("sweep5", 2, 0, 0, 1, 1048576u);  // row bits 8-11 -> real(Z) to d_out
#undef LAUNCH_CK
}

// round 11
// speedup vs baseline: 1.4086x; 1.4086x over previous
#include <cuda_runtime.h>
#include <cstdint>

#define DIM 4096
#define RPC 4               // rows or cols per CTA
#define TPR 128             // threads per smem vector
#define NT  (RPC * TPR)     // 512
#define SMEM_BYTES (RPC * DIM * (int)sizeof(float2))  // 128 KB

// 128 MB complex scratch for W = U x (16B-aligned by type; exonerated R10).
__device__ float4 g_buf[(size_t)DIM * DIM / 2];

__device__ __forceinline__ float2 cmul(float2 a, float2 b) {
    return make_float2(fmaf(a.x, b.x, -a.y * b.y), fmaf(a.x, b.y, a.y * b.x));
}

__device__ __forceinline__ float2 cmadd2(float2 g0, float2 a, float2 g1, float2 b) {
    float re = fmaf(g0.x, a.x, -g0.y * a.y);
    re = fmaf(g1.x, b.x, re);
    re = fmaf(-g1.y, b.y, re);
    float im = fmaf(g0.x, a.y, g0.y * a.x);
    im = fmaf(g1.x, b.y, im);
    im = fmaf(g1.y, b.x, im);
    return make_float2(re, im);
}

// SMEM swizzle within one 4096 vector. Verified conflict-free for all passes.
__device__ __forceinline__ int PHYS(int j) { return j ^ ((j >> 4) & 15); }

// Build all 12 gates (optionally conjugated) into shared. Thread 0 only.
__device__ void build_gates(float2 Gq[12][4], const float* w, int cj) {
    const float WM = 0.63245553203367586640f;  // sqrt(2/5)
    for (int q = 0; q < 12; q++) {
        float hx = 0.5f * w[3 * q + 0] * WM;
        float hy = 0.5f * w[3 * q + 1] * WM;
        float hz = 0.5f * w[3 * q + 2] * WM;
        float cx, sx, cy, sy, cz, sz;
        sincosf(hx, &sx, &cx);
        sincosf(hy, &sy, &cy);
        sincosf(hz, &sz, &cz);
        float2 m0 = make_float2(cy * cx, sy * sx);
        float2 m1 = make_float2(-sy * cx, -cy * sx);
        float2 m2 = make_float2(sy * cx, -cy * sx);
        float2 m3 = make_float2(cy * cx, -sy * sx);
        float2 ez  = make_float2(cz, -sz);
        float2 ezc = make_float2(cz,  sz);
        float2 u0 = cmul(ez, m0),  u1 = cmul(ez, m1);
        float2 u2 = cmul(ezc, m2), u3 = cmul(ezc, m3);
        float sgn = cj ? -1.f : 1.f;
        Gq[q][0] = make_float2(u0.x, sgn * u0.y);
        Gq[q][1] = make_float2(u1.x, sgn * u1.y);
        Gq[q][2] = make_float2(u2.x, sgn * u2.y);
        Gq[q][3] = make_float2(u3.x, sgn * u3.y);
    }
}

// Gates for pass p (transform bits 4p..4p+3). Qubit q acts on bit 11-q.
__device__ __forceinline__ void load_gates(float2 G[4][4], const float2 Gq[12][4], int p) {
#pragma unroll
    for (int s = 0; s < 4; s++) {
        int q = 11 - (4 * p + s);
#pragma unroll
        for (int e = 0; e < 4; e++) G[s][e] = Gq[q][e];
    }
}

__device__ __forceinline__ void bfly16(float2 v[16], const float2 G[4][4]) {
#pragma unroll
    for (int s = 0; s < 4; s++) {
        int str = 1 << s;
#pragma unroll
        for (int k = 0; k < 16; k++) {
            if ((k & str) == 0) {
                float2 a = v[k], b = v[k + str];
                float2 n0 = cmadd2(G[s][0], a, G[s][1], b);
                float2 n1 = cmadd2(G[s][2], a, G[s][3], b);
                v[k] = n0;
                v[k + str] = n1;
            }
        }
    }
}

// Passes 1 and 2 (bits 4..7, 8..11) on the SMEM vector srow with constant XOR sw.
__device__ __forceinline__ void passes_12(float2* srow, const float2 Gq[12][4],
                                          int t, int sw) {
    float2 G[4][4];
    load_gates(G, Gq, 1);
#pragma unroll
    for (int gi = 0; gi < 2; gi++) {
        int g = t + gi * TPR;
        int base = ((g >> 4) << 8) + (g & 15);
        float2 v[16];
#pragma unroll
        for (int i = 0; i < 16; i++) v[i] = srow[PHYS(base + i * 16) ^ sw];
        bfly16(v, G);
#pragma unroll
        for (int i = 0; i < 16; i++) srow[PHYS(base + i * 16) ^ sw] = v[i];
    }
    __syncthreads();
    load_gates(G, Gq, 2);
#pragma unroll
    for (int gi = 0; gi < 2; gi++) {
        int g = t + gi * TPR;
        float2 v[16];
#pragma unroll
        for (int i = 0; i < 16; i++) v[i] = srow[PHYS(g + (i << 8)) ^ sw];
        bfly16(v, G);
#pragma unroll
        for (int i = 0; i < 16; i++) srow[PHYS(g + (i << 8)) ^ sw] = v[i];
    }
    __syncthreads();
}

// ---------------------------------------------------------------------------
// Kernel A: W = U x, column-wise. CTA owns 4 adjacent columns of x.
// Gather real cols -> SMEM complex -> 3 passes (plain gates) -> write W
// row-major to g_buf (32B full sector per (r, 4-col) group).
// ---------------------------------------------------------------------------
__global__ void __launch_bounds__(NT) kernelA(const float* __restrict__ x,
                                              const float* __restrict__ w) {
    extern __shared__ float2 sm[];          // [4 cols][DIM]
    __shared__ float2 Gq[12][4];
    const int tid = threadIdx.x;
    const int c0  = blockIdx.x * RPC;

    if (tid == 0) build_gates(Gq, w, 0 /*plain U*/);

    // Gather 4 columns (16B per 4-thread quad; x is L2-resident).
    __syncthreads();
#pragma unroll
    for (int it = 0; it < (RPC * DIM) / NT; it++) {   // 32 iters
        int idx = it * NT + tid;
        int col = idx & 3;
        int r   = idx >> 2;
        float val = x[(size_t)r * DIM + c0 + col];
        sm[col * DIM + (PHYS(r) ^ (col << 2))] = make_float2(val, 0.f);
    }
    __syncthreads();

    const int row = tid >> 7;        // which column vector this warp group works
    const int t   = tid & (TPR - 1);
    const int sw  = row << 2;
    float2* srow  = sm + row * DIM;

    float2 G[4][4];
    load_gates(G, Gq, 0);
#pragma unroll
    for (int gi = 0; gi < 2; gi++) {
        int g = t + gi * TPR;
        float2 v[16];
#pragma unroll
        for (int i = 0; i < 16; i++) v[i] = srow[PHYS(g * 16 + i) ^ sw];
        bfly16(v, G);
#pragma unroll
        for (int i = 0; i < 16; i++) srow[PHYS(g * 16 + i) ^ sw] = v[i];
    }
    __syncthreads();

    passes_12(srow, Gq, t, sw);

    // Write W row-major: thread owns one r, writes W[r][c0..c0+3] = 32B.
#pragma unroll
    for (int it = 0; it < DIM / NT; it++) {           // 8 iters
        int r = it * NT + tid;
        float2 a = sm[0 * DIM + (PHYS(r) ^ 0)];
        float2 b = sm[1 * DIM + (PHYS(r) ^ 4)];
        float2 c = sm[2 * DIM + (PHYS(r) ^ 8)];
        float2 d = sm[3 * DIM + (PHYS(r) ^ 12)];
        float4* dst = g_buf + ((size_t)r * DIM + c0) / 2;
        dst[0] = make_float4(a.x, a.y, b.x, b.y);
        dst[1] = make_float4(c.x, c.y, d.x, d.y);
    }
}

// ---------------------------------------------------------------------------
// Kernel B: Z = W U^H, row-wise (conj gates). CTA owns 4 adjacent rows of W.
// Coalesced float4 reads fused with pass 0 -> passes 1,2 -> write real(Z)
// rows as float32 (perfectly coalesced; 64 MB total matches out dtype).
// ---------------------------------------------------------------------------
__global__ void __launch_bounds__(NT) kernelB(float* __restrict__ out,
                                              const float* __restrict__ w) {
    extern __shared__ float2 sm[];          // [4 rows][DIM]
    __shared__ float2 Gq[12][4];
    const int tid = threadIdx.x;
    const int row = tid >> 7;
    const int t   = tid & (TPR - 1);
    const int r0  = blockIdx.x * RPC;
    float2* srow  = sm + row * DIM;

    if (tid == 0) build_gates(Gq, w, 1 /*conj U*/);
    __syncthreads();

    float2 G[4][4];
    load_gates(G, Gq, 0);
#pragma unroll
    for (int gi = 0; gi < 2; gi++) {
        int g = t + gi * TPR;
        const float4* src = g_buf + ((size_t)(r0 + row) * DIM + g * 16) / 2;
        float2 v[16];
#pragma unroll
        for (int i = 0; i < 8; i++) {
            float4 f = src[i];
            v[2 * i + 0] = make_float2(f.x, f.y);
            v[2 * i + 1] = make_float2(f.z, f.w);
        }
        bfly16(v, G);
#pragma unroll
        for (int i = 0; i < 16; i++) srow[PHYS(g * 16 + i)] = v[i];
    }
    __syncthreads();

    passes_12(srow, Gq, t, 0);

    // Real-part row write: warp stores 128B contiguous.
#pragma unroll
    for (int k = 0; k < DIM / TPR; k++) {             // 32 iters
        int c = k * TPR + t;
        out[(size_t)(r0 + row) * DIM + c] = srow[PHYS(c)].x;
    }
}

// ---------------------------------------------------------------------------
extern "C" void kernel_launch(void* const* d_in, const int* in_sizes, int n_in,
                              void* d_out, int out_size) {
    // weight = strictly smaller input (sizes confirmed by R8 DIAG: 36 vs 16.7M)
    const float* w;
    const float* x;
    if (in_sizes[0] <= in_sizes[1]) { w = (const float*)d_in[0]; x = (const float*)d_in[1]; }
    else                            { w = (const float*)d_in[1]; x = (const float*)d_in[0]; }

    cudaFuncSetAttribute(kernelA, cudaFuncAttributeMaxDynamicSharedMemorySize, SMEM_BYTES);
    cudaFuncSetAttribute(kernelB, cudaFuncAttributeMaxDynamicSharedMemorySize, SMEM_BYTES);

    kernelA<<<DIM / RPC, NT, SMEM_BYTES>>>(x, w);            // W = U x   -> g_buf
    kernelB<<<DIM / RPC, NT, SMEM_BYTES>>>((float*)d_out, w); // Z = W U^H -> real out
}

// round 12
// speedup vs baseline: 1.6900x; 1.1998x over previous
#include <cuda_runtime.h>
#include <cstdint>

#define DIM 4096

// 128 MB complex scratch for Y = x U^H (float4-typed => 16B-aligned).
__device__ float4 g_buf[(size_t)DIM * DIM / 2];
// Gate matrices: [conj?][qubit][2x2 row-major]
__device__ float2 g_gates[2][12][4];

__device__ __forceinline__ float2 cmul(float2 a, float2 b) {
    return make_float2(fmaf(a.x, b.x, -a.y * b.y), fmaf(a.x, b.y, a.y * b.x));
}

__device__ __forceinline__ float2 cmadd2(float2 g0, float2 a, float2 g1, float2 b) {
    float re = fmaf(g0.x, a.x, -g0.y * a.y);
    re = fmaf(g1.x, b.x, re);
    re = fmaf(-g1.y, b.y, re);
    float im = fmaf(g0.x, a.y, g0.y * a.x);
    im = fmaf(g1.x, b.y, im);
    im = fmaf(g1.y, b.x, im);
    return make_float2(re, im);
}

__device__ __forceinline__ int PHYS(int j) { return j ^ ((j >> 4) & 15); }

// ---------------------------------------------------------------------------
__global__ void prep_kernel(const float* __restrict__ w) {
    int q = threadIdx.x;
    if (q >= 12) return;
    const float WM = 0.63245553203367586640f;  // sqrt(2/5)
    float hx = 0.5f * w[3 * q + 0] * WM;
    float hy = 0.5f * w[3 * q + 1] * WM;
    float hz = 0.5f * w[3 * q + 2] * WM;
    float cx, sx, cy, sy, cz, sz;
    sincosf(hx, &sx, &cx);
    sincosf(hy, &sy, &cy);
    sincosf(hz, &sz, &cz);
    float2 m0 = make_float2(cy * cx, sy * sx);
    float2 m1 = make_float2(-sy * cx, -cy * sx);
    float2 m2 = make_float2(sy * cx, -cy * sx);
    float2 m3 = make_float2(cy * cx, -sy * sx);
    float2 ez  = make_float2(cz, -sz);
    float2 ezc = make_float2(cz,  sz);
    float2 u[4];
    u[0] = cmul(ez, m0);  u[1] = cmul(ez, m1);
    u[2] = cmul(ezc, m2); u[3] = cmul(ezc, m3);
#pragma unroll
    for (int e = 0; e < 4; e++) {
        g_gates[0][q][e] = u[e];
        g_gates[1][q][e] = make_float2(u[e].x, -u[e].y);
    }
}

// Gates for pass p (bits 4p..4p+3); qubit q acts on bit 11-q.
__device__ __forceinline__ void load_gates(float2 G[4][4], int p, int cj) {
#pragma unroll
    for (int s = 0; s < 4; s++) {
        int q = 11 - (4 * p + s);
#pragma unroll
        for (int e = 0; e < 4; e++) G[s][e] = g_gates[cj][q][e];
    }
}

__device__ __forceinline__ void bfly16(float2 v[16], const float2 G[4][4]) {
#pragma unroll
    for (int s = 0; s < 4; s++) {
        int str = 1 << s;
#pragma unroll
        for (int k = 0; k < 16; k++) {
            if ((k & str) == 0) {
                float2 a = v[k], b = v[k + str];
                float2 n0 = cmadd2(G[s][0], a, G[s][1], b);
                float2 n1 = cmadd2(G[s][2], a, G[s][3], b);
                v[k] = n0;
                v[k + str] = n1;
            }
        }
    }
}

// ---------------------------------------------------------------------------
// Kernel A: Y = x U^H, one ROW per CTA, 128 threads, 32KB smem (4+ CTAs/SM).
// Fuses pass0 with the coalesced float4 load of x and pass2 with the
// coalesced complex store of Y (stride-256 per i => 256B/warp contiguous).
// ---------------------------------------------------------------------------
__global__ void __launch_bounds__(128, 4) kernelA(const float* __restrict__ x) {
    extern __shared__ float2 sm[];            // [DIM]
    const int t   = threadIdx.x;              // 0..127
    const int row = blockIdx.x;

    float2 G[4][4];
    // ---- load + pass 0 (bits 0..3) ----
    load_gates(G, 0, 1 /*conj*/);
#pragma unroll
    for (int gi = 0; gi < 2; gi++) {
        int g = t + gi * 128;                 // group 0..255
        const float4* src = (const float4*)(x + (size_t)row * DIM + g * 16);
        float2 v[16];
#pragma unroll
        for (int i = 0; i < 4; i++) {
            float4 f = src[i];
            v[4 * i + 0] = make_float2(f.x, 0.f);
            v[4 * i + 1] = make_float2(f.y, 0.f);
            v[4 * i + 2] = make_float2(f.z, 0.f);
            v[4 * i + 3] = make_float2(f.w, 0.f);
        }
        bfly16(v, G);
#pragma unroll
        for (int i = 0; i < 16; i++) sm[PHYS(g * 16 + i)] = v[i];
    }
    __syncthreads();

    // ---- pass 1 (bits 4..7) ----
    load_gates(G, 1, 1);
#pragma unroll
    for (int gi = 0; gi < 2; gi++) {
        int g = t + gi * 128;
        int base = ((g >> 4) << 8) + (g & 15);
        float2 v[16];
#pragma unroll
        for (int i = 0; i < 16; i++) v[i] = sm[PHYS(base + i * 16)];
        bfly16(v, G);
#pragma unroll
        for (int i = 0; i < 16; i++) sm[PHYS(base + i * 16)] = v[i];
    }
    __syncthreads();

    // ---- pass 2 (bits 8..11) fused with global store ----
    load_gates(G, 2, 1);
    float2* gout = (float2*)g_buf;
#pragma unroll
    for (int gi = 0; gi < 2; gi++) {
        int g = t + gi * 128;
        float2 v[16];
#pragma unroll
        for (int i = 0; i < 16; i++) v[i] = sm[PHYS(g + (i << 8))];
        bfly16(v, G);
#pragma unroll
        for (int i = 0; i < 16; i++)
            gout[(size_t)row * DIM + g + (i << 8)] = v[i];  // coalesced per i
    }
}

// ---------------------------------------------------------------------------
// Kernel B: Z = U Y, TWO adjacent COLUMNS per CTA, 256 threads, 64KB smem
// (2 CTAs/SM). Gather: one float4 per row = both columns' complex (full 16B
// of each sector; neighbor CTA uses the other half via L2). After 3 passes,
// write real parts: one float2 (8B) per row; L2 merges sectors (out fits L2).
// Column c stored in sm[c*DIM + (PHYS(r) ^ (c<<2))].
// ---------------------------------------------------------------------------
__global__ void __launch_bounds__(256, 2) kernelB(float* __restrict__ out) {
    extern __shared__ float2 sm[];            // [2][DIM]
    const int tid = threadIdx.x;
    const int c0  = blockIdx.x * 2;

    // ---- gather 2 columns ----
#pragma unroll
    for (int it = 0; it < DIM / 256; it++) {  // 16 iters
        int r = it * 256 + tid;
        float4 f = g_buf[((size_t)r * DIM + c0) / 2];
        sm[PHYS(r)]              = make_float2(f.x, f.y);
        sm[DIM + (PHYS(r) ^ 4)]  = make_float2(f.z, f.w);
    }
    __syncthreads();

    const int row = tid >> 7;                 // which column vector
    const int t   = tid & 127;
    const int sw  = row << 2;
    float2* srow  = sm + row * DIM;

    float2 G[4][4];
    // ---- pass 0 ----
    load_gates(G, 0, 0 /*plain*/);
#pragma unroll
    for (int gi = 0; gi < 2; gi++) {
        int g = t + gi * 128;
        float2 v[16];
#pragma unroll
        for (int i = 0; i < 16; i++) v[i] = srow[PHYS(g * 16 + i) ^ sw];
        bfly16(v, G);
#pragma unroll
        for (int i = 0; i < 16; i++) srow[PHYS(g * 16 + i) ^ sw] = v[i];
    }
    __syncthreads();

    // ---- pass 1 ----
    load_gates(G, 1, 0);
#pragma unroll
    for (int gi = 0; gi < 2; gi++) {
        int g = t + gi * 128;
        int base = ((g >> 4) << 8) + (g & 15);
        float2 v[16];
#pragma unroll
        for (int i = 0; i < 16; i++) v[i] = srow[PHYS(base + i * 16) ^ sw];
        bfly16(v, G);
#pragma unroll
        for (int i = 0; i < 16; i++) srow[PHYS(base + i * 16) ^ sw] = v[i];
    }
    __syncthreads();

    // ---- pass 2 ----
    load_gates(G, 2, 0);
#pragma unroll
    for (int gi = 0; gi < 2; gi++) {
        int g = t + gi * 128;
        float2 v[16];
#pragma unroll
        for (int i = 0; i < 16; i++) v[i] = srow[PHYS(g + (i << 8)) ^ sw];
        bfly16(v, G);
#pragma unroll
        for (int i = 0; i < 16; i++) srow[PHYS(g + (i << 8)) ^ sw] = v[i];
    }
    __syncthreads();

    // ---- write real(Z) for both columns: 8B per row ----
#pragma unroll
    for (int it = 0; it < DIM / 256; it++) {  // 16 iters
        int r = it * 256 + tid;
        float a = sm[PHYS(r)].x;
        float b = sm[DIM + (PHYS(r) ^ 4)].x;
        *(float2*)(out + (size_t)r * DIM + c0) = make_float2(a, b);
    }
}

// ---------------------------------------------------------------------------
extern "C" void kernel_launch(void* const* d_in, const int* in_sizes, int n_in,
                              void* d_out, int out_size) {
    const float* w;
    const float* x;
    if (in_sizes[0] <= in_sizes[1]) { w = (const float*)d_in[0]; x = (const float*)d_in[1]; }
    else                            { w = (const float*)d_in[1]; x = (const float*)d_in[0]; }

    const int smA = DIM * (int)sizeof(float2);        // 32 KB
    const int smB = 2 * DIM * (int)sizeof(float2);    // 64 KB
    cudaFuncSetAttribute(kernelA, cudaFuncAttributeMaxDynamicSharedMemorySize, smA);
    cudaFuncSetAttribute(kernelB, cudaFuncAttributeMaxDynamicSharedMemorySize, smB);

    prep_kernel<<<1, 32>>>(w);
    kernelA<<<DIM, 128, smA>>>(x);                    // Y = x U^H -> g_buf
    kernelB<<<DIM / 2, 256, smB>>>((float*)d_out);    // Z = U Y   -> real out
}

// round 13
// speedup vs baseline: 1.8039x; 1.0674x over previous
#include <cuda_runtime.h>
#include <cstdint>

#define DIM 4096
typedef unsigned long long u64;

// 128 MB complex scratch for Y = x U^H (float4 => 16B aligned).
__device__ float4 g_buf[(size_t)DIM * DIM / 2];
// Unpacked gates [conj?][qubit][4]: float2 {re, im}  (used by kernelA stage 0)
__device__ float2 g_gates[2][12][4];
// Packed gates for f32x2 math: float4 {re, re, -im, +im} per element
__device__ float4 g_gpk[2][12][4];

// ---------------- f32x2 packed primitives (Blackwell FFMA2) ----------------
__device__ __forceinline__ u64 fma2(u64 a, u64 b, u64 c) {
    u64 d; asm("fma.rn.f32x2 %0, %1, %2, %3;" : "=l"(d) : "l"(a), "l"(b), "l"(c));
    return d;
}
__device__ __forceinline__ u64 mul2(u64 a, u64 b) {
    u64 d; asm("mul.rn.f32x2 %0, %1, %2;" : "=l"(d) : "l"(a), "l"(b));
    return d;
}
__device__ __forceinline__ u64 pack2(float lo, float hi) {
    u64 d; asm("mov.b64 %0, {%1, %2};" : "=l"(d) : "f"(lo), "f"(hi));
    return d;
}
__device__ __forceinline__ u64 swp2(u64 a) {
    unsigned lo, hi;
    asm("mov.b64 {%0, %1}, %2;" : "=r"(lo), "=r"(hi) : "l"(a));
    u64 d; asm("mov.b64 %0, {%1, %2};" : "=l"(d) : "r"(hi), "r"(lo));
    return d;
}
__device__ __forceinline__ float lo32(u64 a) {
    unsigned lo, hi;
    asm("mov.b64 {%0, %1}, %2;" : "=r"(lo), "=r"(hi) : "l"(a));
    return __uint_as_float(lo);
}

__device__ __forceinline__ float2 cmulh(float2 a, float2 b) {
    return make_float2(fmaf(a.x, b.x, -a.y * b.y), fmaf(a.x, b.y, a.y * b.x));
}

__device__ __forceinline__ int PHYS(int j) { return j ^ ((j >> 4) & 15); }

// ---------------------------------------------------------------------------
__global__ void prep_kernel(const float* __restrict__ w) {
    int q = threadIdx.x;
    if (q >= 12) return;
    const float WM = 0.63245553203367586640f;  // sqrt(2/5)
    float hx = 0.5f * w[3 * q + 0] * WM;
    float hy = 0.5f * w[3 * q + 1] * WM;
    float hz = 0.5f * w[3 * q + 2] * WM;
    float cx, sx, cy, sy, cz, sz;
    sincosf(hx, &sx, &cx);
    sincosf(hy, &sy, &cy);
    sincosf(hz, &sz, &cz);
    float2 m0 = make_float2(cy * cx, sy * sx);
    float2 m1 = make_float2(-sy * cx, -cy * sx);
    float2 m2 = make_float2(sy * cx, -cy * sx);
    float2 m3 = make_float2(cy * cx, -sy * sx);
    float2 ez  = make_float2(cz, -sz);
    float2 ezc = make_float2(cz,  sz);
    float2 u[4];
    u[0] = cmulh(ez, m0);  u[1] = cmulh(ez, m1);
    u[2] = cmulh(ezc, m2); u[3] = cmulh(ezc, m3);
#pragma unroll
    for (int e = 0; e < 4; e++) {
        g_gates[0][q][e] = u[e];
        g_gates[1][q][e] = make_float2(u[e].x, -u[e].y);
        // plain: gate {re, im}  -> gx={re,re}, gyn={-im,+im}
        g_gpk[0][q][e] = make_float4(u[e].x, u[e].x, -u[e].y,  u[e].y);
        // conj: gate {re,-im}   -> gyn={+im,-im}
        g_gpk[1][q][e] = make_float4(u[e].x, u[e].x,  u[e].y, -u[e].y);
    }
}

// ---------------------------------------------------------------------------
// Packed butterfly stages s0..3 of pass `pass` on 16 packed complex values.
// Per pair: 8 fma-pipe slots (6xFMA2 + 2xMUL2) + 2 half-swaps (alu pipe).
// ---------------------------------------------------------------------------
__device__ __forceinline__ void bstages(u64 v[16], int pass, int cj, int s0) {
#pragma unroll
    for (int s = 0; s < 4; s++) {
        if (s < s0) continue;
        int q = 11 - (4 * pass + s);
        const ulonglong2* gp = (const ulonglong2*)g_gpk[cj][q];
        u64 gx0 = gp[0].x, gy0 = gp[0].y, gx1 = gp[1].x, gy1 = gp[1].y;
        u64 gx2 = gp[2].x, gy2 = gp[2].y, gx3 = gp[3].x, gy3 = gp[3].y;
        int str = 1 << s;
#pragma unroll
        for (int k = 0; k < 16; k++) {
            if ((k & str) == 0) {
                u64 a = v[k], b = v[k + str];
                u64 sa = swp2(a), sb = swp2(b);
                v[k]       = fma2(gx0, a, fma2(gy0, sa, fma2(gx1, b, mul2(gy1, sb))));
                v[k + str] = fma2(gx2, a, fma2(gy2, sa, fma2(gx3, b, mul2(gy3, sb))));
            }
        }
    }
}

// ---------------------------------------------------------------------------
// Kernel A: Y = x U^H, one ROW per CTA, 128 threads, 32KB smem.
// Stage 0 fused with the coalesced float4 load of x, using the REAL-input
// shortcut (2 packed slots per output). Pass 2 fused with the global store.
// ---------------------------------------------------------------------------
__global__ void __launch_bounds__(128, 4) kernelA(const float* __restrict__ x) {
    extern __shared__ float2 smf[];
    u64* sm = (u64*)smf;                      // [DIM] packed complex
    const int t   = threadIdx.x;
    const int row = blockIdx.x;

    // ---- load + pass 0 (bits 0..3), conj gates ----
    const u64* ge = (const u64*)g_gates[1][11];   // stage 0 -> qubit 11
#pragma unroll
    for (int gi = 0; gi < 2; gi++) {
        int g = t + gi * 128;                 // group 0..255
        const float4* src = (const float4*)(x + (size_t)row * DIM + g * 16);
        float f[16];
#pragma unroll
        for (int i = 0; i < 4; i++) {
            float4 q4 = src[i];
            f[4 * i + 0] = q4.x; f[4 * i + 1] = q4.y;
            f[4 * i + 2] = q4.z; f[4 * i + 3] = q4.w;
        }
        u64 v[16];
        // real-input stage 0: pairs (2k, 2k+1)
#pragma unroll
        for (int k = 0; k < 16; k += 2) {
            u64 aa = pack2(f[k], f[k]);
            u64 bb = pack2(f[k + 1], f[k + 1]);
            v[k]     = fma2(ge[0], aa, mul2(ge[1], bb));
            v[k + 1] = fma2(ge[2], aa, mul2(ge[3], bb));
        }
        bstages(v, 0, 1, 1);                  // stages 1..3 of pass 0
#pragma unroll
        for (int i = 0; i < 16; i++) sm[PHYS(g * 16 + i)] = v[i];
    }
    __syncthreads();

    // ---- pass 1 (bits 4..7) ----
#pragma unroll
    for (int gi = 0; gi < 2; gi++) {
        int g = t + gi * 128;
        int base = ((g >> 4) << 8) + (g & 15);
        u64 v[16];
#pragma unroll
        for (int i = 0; i < 16; i++) v[i] = sm[PHYS(base + i * 16)];
        bstages(v, 1, 1, 0);
#pragma unroll
        for (int i = 0; i < 16; i++) sm[PHYS(base + i * 16)] = v[i];
    }
    __syncthreads();

    // ---- pass 2 (bits 8..11) fused with global store ----
    u64* gout = (u64*)g_buf;
#pragma unroll
    for (int gi = 0; gi < 2; gi++) {
        int g = t + gi * 128;
        u64 v[16];
#pragma unroll
        for (int i = 0; i < 16; i++) v[i] = sm[PHYS(g + (i << 8))];
        bstages(v, 2, 1, 0);
#pragma unroll
        for (int i = 0; i < 16; i++)
            gout[(size_t)row * DIM + g + (i << 8)] = v[i];  // coalesced per i
    }
}

// ---------------------------------------------------------------------------
// Kernel B: Z = U Y, TWO adjacent COLUMNS per CTA, 256 threads, 64KB smem.
// Gather one float4 per row (both columns), 3 packed passes, write real parts.
// Column c lives in sm[c*DIM + (PHYS(r) ^ (c<<2))].
// ---------------------------------------------------------------------------
__global__ void __launch_bounds__(256, 2) kernelB(float* __restrict__ out) {
    extern __shared__ float2 smf[];
    u64* sm = (u64*)smf;                      // [2][DIM]
    const int tid = threadIdx.x;
    const int c0  = blockIdx.x * 2;

    // ---- gather 2 columns ----
#pragma unroll
    for (int it = 0; it < DIM / 256; it++) {  // 16 iters
        int r = it * 256 + tid;
        float4 f = g_buf[((size_t)r * DIM + c0) / 2];
        sm[PHYS(r)]             = pack2(f.x, f.y);
        sm[DIM + (PHYS(r) ^ 4)] = pack2(f.z, f.w);
    }
    __syncthreads();

    const int row = tid >> 7;
    const int t   = tid & 127;
    const int sw  = row << 2;
    u64* srow     = sm + row * DIM;

    // ---- pass 0 ----
#pragma unroll
    for (int gi = 0; gi < 2; gi++) {
        int g = t + gi * 128;
        u64 v[16];
#pragma unroll
        for (int i = 0; i < 16; i++) v[i] = srow[PHYS(g * 16 + i) ^ sw];
        bstages(v, 0, 0, 0);
#pragma unroll
        for (int i = 0; i < 16; i++) srow[PHYS(g * 16 + i) ^ sw] = v[i];
    }
    __syncthreads();

    // ---- pass 1 ----
#pragma unroll
    for (int gi = 0; gi < 2; gi++) {
        int g = t + gi * 128;
        int base = ((g >> 4) << 8) + (g & 15);
        u64 v[16];
#pragma unroll
        for (int i = 0; i < 16; i++) v[i] = srow[PHYS(base + i * 16) ^ sw];
        bstages(v, 1, 0, 0);
#pragma unroll
        for (int i = 0; i < 16; i++) srow[PHYS(base + i * 16) ^ sw] = v[i];
    }
    __syncthreads();

    // ---- pass 2 ----
#pragma unroll
    for (int gi = 0; gi < 2; gi++) {
        int g = t + gi * 128;
        u64 v[16];
#pragma unroll
        for (int i = 0; i < 16; i++) v[i] = srow[PHYS(g + (i << 8)) ^ sw];
        bstages(v, 2, 0, 0);
#pragma unroll
        for (int i = 0; i < 16; i++) srow[PHYS(g + (i << 8)) ^ sw] = v[i];
    }
    __syncthreads();

    // ---- write real(Z) for both columns: 8B per row ----
#pragma unroll
    for (int it = 0; it < DIM / 256; it++) {  // 16 iters
        int r = it * 256 + tid;
        float a = lo32(sm[PHYS(r)]);
        float b = lo32(sm[DIM + (PHYS(r) ^ 4)]);
        *(float2*)(out + (size_t)r * DIM + c0) = make_float2(a, b);
    }
}

// ---------------------------------------------------------------------------
extern "C" void kernel_launch(void* const* d_in, const int* in_sizes, int n_in,
                              void* d_out, int out_size) {
    const float* w;
    const float* x;
    if (in_sizes[0] <= in_sizes[1]) { w = (const float*)d_in[0]; x = (const float*)d_in[1]; }
    else                            { w = (const float*)d_in[1]; x = (const float*)d_in[0]; }

    const int smA = DIM * (int)sizeof(float2);        // 32 KB
    const int smB = 2 * DIM * (int)sizeof(float2);    // 64 KB
    cudaFuncSetAttribute(kernelA, cudaFuncAttributeMaxDynamicSharedMemorySize, smA);
    cudaFuncSetAttribute(kernelB, cudaFuncAttributeMaxDynamicSharedMemorySize, smB);

    prep_kernel<<<1, 32>>>(w);
    kernelA<<<DIM, 128, smA>>>(x);                    // Y = x U^H -> g_buf
    kernelB<<<DIM / 2, 256, smB>>>((float*)d_out);    // Z = U Y   -> real out
}